// round 2
// baseline (speedup 1.0000x reference)
#include <cuda_runtime.h>

// ---------------------------------------------------------------------------
// NormEMAVectorQuantizer for GB300 (sm_103a)
//   inputs : z [32,32,16,16] f32 (262144), embedding [8192,32] f32 (262144),
//            cluster_sizes [8192] f32
//   output : concat( z_q[262144], loss[1], token_ids[8192],
//                    new_embedding[262144], new_cluster_sizes[8192] ) = 540673 f32
// ---------------------------------------------------------------------------

#define N_VEC   8192      // B*H*W query vectors
#define N_TOK   8192      // codebook size
#define CDIM    32
#define KSPLIT  8
#define QB      128       // queries per argmax block
#define KT      128       // codes per smem tile

#define OFF_ZQ    0
#define OFF_LOSS  262144
#define OFF_TOK   262145
#define OFF_EMB   270337
#define OFF_CSZ   532481

// scratch (no allocations allowed -> __device__ globals)
__device__ float g_zn[N_VEC * CDIM];
__device__ float g_bestv[KSPLIT * N_VEC];
__device__ int   g_besti[KSPLIT * N_VEC];
__device__ float g_bins[N_TOK];
__device__ float g_esum[N_TOK * CDIM];
__device__ float g_loss;

// ---- packed f32x2 helpers (FFMA2: 2 fp32 MACs per instruction; ptxas never
// ---- auto-fuses this, only reachable via PTX fma.rn.f32x2) -----------------
static __device__ __forceinline__ unsigned long long fma2(
    unsigned long long a, unsigned long long b, unsigned long long c) {
    unsigned long long d;
    asm("fma.rn.f32x2 %0, %1, %2, %3;" : "=l"(d) : "l"(a), "l"(b), "l"(c));
    return d;
}
static __device__ __forceinline__ unsigned long long pack2(float lo, float hi) {
    unsigned long long r;
    asm("mov.b64 %0, {%1, %2};" : "=l"(r)
        : "r"(__float_as_uint(lo)), "r"(__float_as_uint(hi)));
    return r;
}
static __device__ __forceinline__ void unpack2(unsigned long long v, float& lo, float& hi) {
    unsigned int a, b;
    asm("mov.b64 {%0, %1}, %2;" : "=r"(a), "=r"(b) : "l"(v));
    lo = __uint_as_float(a);
    hi = __uint_as_float(b);
}

// ---------------------------------------------------------------------------
// K0: zero per-call scratch (graph is replayed; must be deterministic)
// ---------------------------------------------------------------------------
__global__ void k_zero() {
    int i = blockIdx.x * blockDim.x + threadIdx.x;
    if (i < N_TOK) g_bins[i] = 0.0f;
    if (i < N_TOK * CDIM) g_esum[i] = 0.0f;
    if (i == 0) g_loss = 0.0f;
}

// ---------------------------------------------------------------------------
// K1: channels-last transpose + L2-normalize -> g_zn [N_VEC][32] row-major
// z layout: z[((b*32+c)*16+h)*16+w]; vector n = b*256 + (h*16+w)
// ---------------------------------------------------------------------------
__global__ __launch_bounds__(256) void k_norm(const float* __restrict__ z) {
    int n  = blockIdx.x * 256 + threadIdx.x;   // grid = 32
    int b  = n >> 8;
    int hw = n & 255;
    const float* src = z + b * (CDIM * 256) + hw;
    float r[CDIM];
    float ss = 0.0f;
#pragma unroll
    for (int c = 0; c < CDIM; c++) {
        float v = src[c * 256];                // coalesced across threads (hw)
        r[c] = v;
        ss += v * v;
    }
    float inv = 1.0f / fmaxf(sqrtf(ss), 1e-12f);
    float4* dst = (float4*)(g_zn + n * CDIM);
#pragma unroll
    for (int j = 0; j < 8; j++)
        dst[j] = make_float4(r[4*j] * inv, r[4*j+1] * inv, r[4*j+2] * inv, r[4*j+3] * inv);
}

// ---------------------------------------------------------------------------
// K2: split-K argmax of cosine similarity, packed-f32x2 FMA mainloop.
// grid (64, 8): blockIdx.x = query tile (128 queries, 1 thread each),
//               blockIdx.y = K split (1024 codes each).
// smem holds the code tile TRANSPOSED sm[c][k] so one broadcast LDS.128
// feeds 4 codes (2 f32x2 accumulator chains). 16 FFMA2 per code = the floor.
// ---------------------------------------------------------------------------
__global__ __launch_bounds__(128) void k_argmax(const float* __restrict__ emb) {
    __shared__ float sm[CDIM][KT];
    int qbase = blockIdx.x * QB;
    int ks    = blockIdx.y;
    int t     = threadIdx.x;

    // query vector, each channel duplicated into both f32x2 lanes
    unsigned long long qd[CDIM];
    const float4* qr = (const float4*)(g_zn + (qbase + t) * CDIM);
#pragma unroll
    for (int j = 0; j < 8; j++) {
        float4 v = qr[j];
        qd[4*j+0] = pack2(v.x, v.x);
        qd[4*j+1] = pack2(v.y, v.y);
        qd[4*j+2] = pack2(v.z, v.z);
        qd[4*j+3] = pack2(v.w, v.w);
    }

    float best = -3.402823466e38f;
    int   bi   = 0;
    int   kbase0 = ks * (N_TOK / KSPLIT);

    for (int tile = 0; tile < (N_TOK / KSPLIT) / KT; tile++) {
        int kb = kbase0 + tile * KT;
        // cooperative transposed tile load: thread t owns code row kb+t
        {
            const float4* src = (const float4*)(emb + (kb + t) * CDIM);
#pragma unroll
            for (int j = 0; j < 8; j++) {
                float4 v = src[j];
                sm[4*j+0][t] = v.x;   // consecutive addrs across warp -> no conflicts
                sm[4*j+1][t] = v.y;
                sm[4*j+2][t] = v.z;
                sm[4*j+3][t] = v.w;
            }
        }
        __syncthreads();

#pragma unroll 1
        for (int k8 = 0; k8 < KT; k8 += 8) {
            unsigned long long a0 = 0ull, a1 = 0ull, a2 = 0ull, a3 = 0ull;
#pragma unroll
            for (int c = 0; c < CDIM; c++) {
                // broadcast loads: all lanes read the same address
                ulonglong2 e0 = *(const ulonglong2*)&sm[c][k8];
                ulonglong2 e1 = *(const ulonglong2*)&sm[c][k8 + 4];
                a0 = fma2(qd[c], e0.x, a0);
                a1 = fma2(qd[c], e0.y, a1);
                a2 = fma2(qd[c], e1.x, a2);
                a3 = fma2(qd[c], e1.y, a3);
            }
            float v0, v1, v2, v3, v4, v5, v6, v7;
            unpack2(a0, v0, v1); unpack2(a1, v2, v3);
            unpack2(a2, v4, v5); unpack2(a3, v6, v7);
            int k0 = kb + k8;
            // strict > with ascending k == jnp.argmax first-max tie rule
            if (v0 > best) { best = v0; bi = k0 + 0; }
            if (v1 > best) { best = v1; bi = k0 + 1; }
            if (v2 > best) { best = v2; bi = k0 + 2; }
            if (v3 > best) { best = v3; bi = k0 + 3; }
            if (v4 > best) { best = v4; bi = k0 + 4; }
            if (v5 > best) { best = v5; bi = k0 + 5; }
            if (v6 > best) { best = v6; bi = k0 + 6; }
            if (v7 > best) { best = v7; bi = k0 + 7; }
        }
        __syncthreads();
    }
    g_bestv[ks * N_VEC + qbase + t] = best;
    g_besti[ks * N_VEC + qbase + t] = bi;
}

// ---------------------------------------------------------------------------
// K3: combine split-K partials, emit token ids + z_q, scatter EMA stats, loss
// ---------------------------------------------------------------------------
__global__ __launch_bounds__(256) void k_assign(const float* __restrict__ emb,
                                                float* __restrict__ out) {
    int n = blockIdx.x * 256 + threadIdx.x;    // grid = 32
    float best = -3.402823466e38f;
    int bi = 0;
#pragma unroll
    for (int s = 0; s < KSPLIT; s++) {         // ascending split keeps first-max
        float v = g_bestv[s * N_VEC + n];
        if (v > best) { best = v; bi = g_besti[s * N_VEC + n]; }
    }
    out[OFF_TOK + n] = (float)bi;

    int b = n >> 8, hw = n & 255;
    const float* e    = emb + bi * CDIM;
    const float* zrow = g_zn + n * CDIM;
    float lsum = 0.0f;
#pragma unroll
    for (int c = 0; c < CDIM; c++) {
        float ev = e[c];
        float zv = zrow[c];
        out[OFF_ZQ + (b * CDIM + c) * 256 + hw] = ev;   // z_q (== straight-through fwd)
        float d = ev - zv;
        lsum += d * d;
        atomicAdd(&g_esum[bi * CDIM + c], zv);
    }
    atomicAdd(&g_bins[bi], 1.0f);
#pragma unroll
    for (int o = 16; o > 0; o >>= 1)
        lsum += __shfl_xor_sync(0xffffffffu, lsum, o);
    if ((threadIdx.x & 31) == 0) atomicAdd(&g_loss, lsum);
}

// ---------------------------------------------------------------------------
// K4: EMA codebook update (warp per token, lane = channel) + loss write
// ---------------------------------------------------------------------------
__global__ __launch_bounds__(256) void k_update(const float* __restrict__ emb,
                                                const float* __restrict__ csz,
                                                float* __restrict__ out) {
    int gtid = blockIdx.x * 256 + threadIdx.x; // grid = 1024 -> 8192 warps
    int k    = gtid >> 5;
    int lane = gtid & 31;

    float bcount = g_bins[k];
    if (lane == 0)
        out[OFF_CSZ + k] = csz[k] * 0.99f + 0.01f * bcount;

    bool  zero = (bcount == 0.0f);
    float bc   = zero ? 1.0f : bcount;
    float m    = g_esum[k * CDIM + lane] / bc;
    float ss   = m * m;
#pragma unroll
    for (int o = 16; o > 0; o >>= 1)
        ss += __shfl_xor_sync(0xffffffffu, ss, o);
    float en = m / fmaxf(sqrtf(ss), 1e-12f);

    float ev = emb[k * CDIM + lane];
    if (zero) en = ev;
    float v  = ev * 0.99f + 0.01f * en;
    float s2 = v * v;
#pragma unroll
    for (int o = 16; o > 0; o >>= 1)
        s2 += __shfl_xor_sync(0xffffffffu, s2, o);
    out[OFF_EMB + k * CDIM + lane] = v / fmaxf(sqrtf(s2), 1e-12f);

    if (gtid == 0)
        out[OFF_LOSS] = g_loss * (1.0f / (float)(N_VEC * CDIM));  // BETA = 1
}

// ---------------------------------------------------------------------------
extern "C" void kernel_launch(void* const* d_in, const int* in_sizes, int n_in,
                              void* d_out, int out_size) {
    const float* z   = (const float*)d_in[0];
    const float* emb = (const float*)d_in[1];
    const float* csz = (const float*)d_in[2];
    float* out = (float*)d_out;

    k_zero<<<(N_TOK * CDIM + 255) / 256, 256>>>();
    k_norm<<<N_VEC / 256, 256>>>(z);
    dim3 grid_am(N_VEC / QB, KSPLIT);
    k_argmax<<<grid_am, 128>>>(emb);
    k_assign<<<N_VEC / 256, 256>>>(emb, out);
    k_update<<<(N_TOK * 32) / 256, 256>>>(emb, csz, out);
}

// round 3
// speedup vs baseline: 1.1050x; 1.1050x over previous
#include <cuda_runtime.h>

// ---------------------------------------------------------------------------
// NormEMAVectorQuantizer for GB300 (sm_103a)  — round 3
//   out = concat( z_q[262144], loss[1], token_ids[8192],
//                 new_embedding[262144], new_cluster_sizes[8192] ) = 540673 f32
// ---------------------------------------------------------------------------

#define N_VEC   8192
#define N_TOK   8192
#define CDIM    32
#define KSPLIT  8
#define QB      128
#define KT      128

#define OFF_ZQ    0
#define OFF_LOSS  262144
#define OFF_TOK   262145
#define OFF_EMB   270337
#define OFF_CSZ   532481

// scratch (__device__ globals; no allocations allowed)
__device__ float              g_zn[N_VEC * CDIM];
__device__ unsigned long long g_key[N_VEC];        // packed (ordered-val | 8191-k)
__device__ float              g_bins[N_TOK];
__device__ float              g_esum[N_TOK * CDIM];
__device__ float              g_loss;

// ---- packed f32x2 helpers --------------------------------------------------
static __device__ __forceinline__ unsigned long long fma2(
    unsigned long long a, unsigned long long b, unsigned long long c) {
    unsigned long long d;
    asm("fma.rn.f32x2 %0, %1, %2, %3;" : "=l"(d) : "l"(a), "l"(b), "l"(c));
    return d;
}
static __device__ __forceinline__ unsigned long long pack2(float lo, float hi) {
    unsigned long long r;
    asm("mov.b64 %0, {%1, %2};" : "=l"(r)
        : "r"(__float_as_uint(lo)), "r"(__float_as_uint(hi)));
    return r;
}
static __device__ __forceinline__ void unpack2(unsigned long long v, float& lo, float& hi) {
    unsigned int a, b;
    asm("mov.b64 {%0, %1}, %2;" : "=r"(a), "=r"(b) : "l"(v));
    lo = __uint_as_float(a);
    hi = __uint_as_float(b);
}

// monotone float -> uint map (preserves total order incl. negatives)
static __device__ __forceinline__ unsigned int ordered_u32(float v) {
    unsigned int b = __float_as_uint(v);
    return (b & 0x80000000u) ? ~b : (b | 0x80000000u);
}

// ---------------------------------------------------------------------------
// K1: prep = (a) warp-per-vector transpose+L2norm of z, (b) zero scratch.
// grid = NORM_BLKS + ZERO_BLKS, 256 threads.
// ---------------------------------------------------------------------------
#define NORM_BLKS  (N_VEC / 8)                       // 1024 (8 warps/block)
#define ZERO_ITEMS (N_TOK * CDIM + N_TOK + N_TOK)    // esum + bins + key
#define ZERO_BLKS  ((ZERO_ITEMS + 255) / 256)        // 1088

__global__ __launch_bounds__(256) void k_prep(const float* __restrict__ z) {
    if (blockIdx.x < NORM_BLKS) {
        int warp = threadIdx.x >> 5;
        int lane = threadIdx.x & 31;                 // = channel c
        int n    = blockIdx.x * 8 + warp;
        int b    = n >> 8, hw = n & 255;
        float v  = z[b * (CDIM * 256) + lane * 256 + hw];
        float ss = v * v;
#pragma unroll
        for (int o = 16; o > 0; o >>= 1)
            ss += __shfl_xor_sync(0xffffffffu, ss, o);
        float inv = 1.0f / fmaxf(sqrtf(ss), 1e-12f);
        g_zn[n * CDIM + lane] = v * inv;             // coalesced
    } else {
        int i = (blockIdx.x - NORM_BLKS) * 256 + threadIdx.x;
        if (i < N_TOK * CDIM) g_esum[i] = 0.0f;
        else if (i < N_TOK * CDIM + N_TOK) g_bins[i - N_TOK * CDIM] = 0.0f;
        else if (i < ZERO_ITEMS) g_key[i - N_TOK * CDIM - N_TOK] = 0ull;
        if (i == 0) g_loss = 0.0f;
    }
}

// ---------------------------------------------------------------------------
// K2: split-K argmax, packed-f32x2 FMA mainloop, per-thread result merged
//     across splits with a single 64-bit atomicMax (order-independent,
//     first-max tie rule preserved via (8191-k) low bits).
// grid (64, 8), 128 threads: thread = 1 query, blockIdx.y = K split (1024).
// ---------------------------------------------------------------------------
__global__ __launch_bounds__(128) void k_argmax(const float* __restrict__ emb) {
    __shared__ float sm[CDIM][KT];
    int qbase = blockIdx.x * QB;
    int ks    = blockIdx.y;
    int t     = threadIdx.x;

    unsigned long long qd[CDIM];
    const float4* qr = (const float4*)(g_zn + (qbase + t) * CDIM);
#pragma unroll
    for (int j = 0; j < 8; j++) {
        float4 v = qr[j];
        qd[4*j+0] = pack2(v.x, v.x);
        qd[4*j+1] = pack2(v.y, v.y);
        qd[4*j+2] = pack2(v.z, v.z);
        qd[4*j+3] = pack2(v.w, v.w);
    }

    float best = -3.402823466e38f;
    int   bi   = 0;
    int   kbase0 = ks * (N_TOK / KSPLIT);

    for (int tile = 0; tile < (N_TOK / KSPLIT) / KT; tile++) {
        int kb = kbase0 + tile * KT;
        {
            const float4* src = (const float4*)(emb + (kb + t) * CDIM);
#pragma unroll
            for (int j = 0; j < 8; j++) {
                float4 v = src[j];
                sm[4*j+0][t] = v.x;
                sm[4*j+1][t] = v.y;
                sm[4*j+2][t] = v.z;
                sm[4*j+3][t] = v.w;
            }
        }
        __syncthreads();

#pragma unroll 1
        for (int k8 = 0; k8 < KT; k8 += 8) {
            unsigned long long a0 = 0ull, a1 = 0ull, a2 = 0ull, a3 = 0ull;
#pragma unroll
            for (int c = 0; c < CDIM; c++) {
                ulonglong2 e0 = *(const ulonglong2*)&sm[c][k8];
                ulonglong2 e1 = *(const ulonglong2*)&sm[c][k8 + 4];
                a0 = fma2(qd[c], e0.x, a0);
                a1 = fma2(qd[c], e0.y, a1);
                a2 = fma2(qd[c], e1.x, a2);
                a3 = fma2(qd[c], e1.y, a3);
            }
            float v0, v1, v2, v3, v4, v5, v6, v7;
            unpack2(a0, v0, v1); unpack2(a1, v2, v3);
            unpack2(a2, v4, v5); unpack2(a3, v6, v7);
            int k0 = kb + k8;
            if (v0 > best) { best = v0; bi = k0 + 0; }
            if (v1 > best) { best = v1; bi = k0 + 1; }
            if (v2 > best) { best = v2; bi = k0 + 2; }
            if (v3 > best) { best = v3; bi = k0 + 3; }
            if (v4 > best) { best = v4; bi = k0 + 4; }
            if (v5 > best) { best = v5; bi = k0 + 5; }
            if (v6 > best) { best = v6; bi = k0 + 6; }
            if (v7 > best) { best = v7; bi = k0 + 7; }
        }
        __syncthreads();
    }

    unsigned long long key =
        ((unsigned long long)ordered_u32(best) << 32) |
        (unsigned int)(N_TOK - 1 - bi);
    atomicMax(&g_key[qbase + t], key);
}

// ---------------------------------------------------------------------------
// K3: scatter epilogue over 262144 threads: z_q (coalesced), token ids,
//     EMA scatter (1 spread REDG each), block-reduced loss.
// thread g -> b=g>>13, c=(g>>8)&31, hw=g&255; out[OFF_ZQ+g] is exactly z_q.
// ---------------------------------------------------------------------------
__global__ __launch_bounds__(256) void k_scatter(const float* __restrict__ emb,
                                                 float* __restrict__ out) {
    __shared__ float red[8];
    int g  = blockIdx.x * 256 + threadIdx.x;
    int b  = g >> 13;
    int c  = (g >> 8) & 31;
    int hw = g & 255;
    int n  = b * 256 + hw;

    unsigned long long key = g_key[n];
    int bi = (N_TOK - 1) - (int)(unsigned int)(key & 0xffffffffu);

    float ev = emb[bi * CDIM + c];
    float zv = g_zn[n * CDIM + c];
    out[OFF_ZQ + g] = ev;
    if (c == 0) {
        out[OFF_TOK + n] = (float)bi;
        atomicAdd(&g_bins[bi], 1.0f);
    }
    atomicAdd(&g_esum[bi * CDIM + c], zv);

    float d = ev - zv;
    float lsum = d * d;
#pragma unroll
    for (int o = 16; o > 0; o >>= 1)
        lsum += __shfl_xor_sync(0xffffffffu, lsum, o);
    if ((threadIdx.x & 31) == 0) red[threadIdx.x >> 5] = lsum;
    __syncthreads();
    if (threadIdx.x == 0) {
        float s = 0.0f;
#pragma unroll
        for (int w = 0; w < 8; w++) s += red[w];
        atomicAdd(&g_loss, s);
    }
}

// ---------------------------------------------------------------------------
// K4: EMA codebook update (warp per token, lane = channel) + loss write
// ---------------------------------------------------------------------------
__global__ __launch_bounds__(256) void k_update(const float* __restrict__ emb,
                                                const float* __restrict__ csz,
                                                float* __restrict__ out) {
    int gtid = blockIdx.x * 256 + threadIdx.x;
    int k    = gtid >> 5;
    int lane = gtid & 31;

    float bcount = g_bins[k];
    if (lane == 0)
        out[OFF_CSZ + k] = csz[k] * 0.99f + 0.01f * bcount;

    bool  zero = (bcount == 0.0f);
    float bc   = zero ? 1.0f : bcount;
    float m    = g_esum[k * CDIM + lane] / bc;
    float ss   = m * m;
#pragma unroll
    for (int o = 16; o > 0; o >>= 1)
        ss += __shfl_xor_sync(0xffffffffu, ss, o);
    float en = m / fmaxf(sqrtf(ss), 1e-12f);

    float ev = emb[k * CDIM + lane];
    if (zero) en = ev;
    float v  = ev * 0.99f + 0.01f * en;
    float s2 = v * v;
#pragma unroll
    for (int o = 16; o > 0; o >>= 1)
        s2 += __shfl_xor_sync(0xffffffffu, s2, o);
    out[OFF_EMB + k * CDIM + lane] = v / fmaxf(sqrtf(s2), 1e-12f);

    if (gtid == 0)
        out[OFF_LOSS] = g_loss * (1.0f / (float)(N_VEC * CDIM));
}

// ---------------------------------------------------------------------------
extern "C" void kernel_launch(void* const* d_in, const int* in_sizes, int n_in,
                              void* d_out, int out_size) {
    const float* z   = (const float*)d_in[0];
    const float* emb = (const float*)d_in[1];
    const float* csz = (const float*)d_in[2];
    float* out = (float*)d_out;

    k_prep<<<NORM_BLKS + ZERO_BLKS, 256>>>(z);
    dim3 grid_am(N_VEC / QB, KSPLIT);
    k_argmax<<<grid_am, 128>>>(emb);
    k_scatter<<<(N_VEC * CDIM) / 256, 256>>>(emb, out);
    k_update<<<(N_TOK * CDIM) / 256, 256>>>(emb, csz, out);
}